// round 9
// baseline (speedup 1.0000x reference)
#include <cuda_runtime.h>
#include <stdint.h>

#define NUM_LABELS 100000
#define EMBED      128
#define NTOK       (16 * 4096)

#define BIN_LABELS 64
#define NBINS      ((NUM_LABELS + BIN_LABELS - 1) / BIN_LABELS)   // 1563
#define CAP        1024                                            // slots per bin (mean load 42)

// __device__ scratch (no cudaMalloc). Zero-initialized at module load;
// fused_kernel resets cursors after use so every call starts from zeros.
__device__ int g_cursor[NBINS];
__device__ int g_list[NBINS * CAP];    // packed entries: (token << 6) | local_label

// 4-byte cp.async with runtime src-size (0 => zero-fill, no gmem access)
__device__ __forceinline__ void cp_async_4(uint32_t smem_addr, const void* gptr, int src_sz) {
    asm volatile("cp.async.ca.shared.global [%0], [%1], 4, %2;\n"
                 :: "r"(smem_addr), "l"(gptr), "r"(src_sz) : "memory");
}
__device__ __forceinline__ void cp_async_commit_wait_all() {
    asm volatile("cp.async.commit_group;\n"
                 "cp.async.wait_group 0;\n" ::: "memory");
}
__device__ __forceinline__ uint32_t smem_u32(const void* p) {
    uint32_t a;
    asm("{ .reg .u64 t; cvta.to.shared.u64 t, %1; cvt.u32.u64 %0, t; }" : "=r"(a) : "l"(p));
    return a;
}

// ---------------------------------------------------------------------------
// K1: bin tokens by 64-label range. entry = (token << 6) | (label % 64).
//     Overflow (pos >= CAP, impossible for this input) handled inline.
// ---------------------------------------------------------------------------
__global__ __launch_bounds__(256) void bin_kernel(const int* __restrict__ X,
                                                  const float* __restrict__ W,
                                                  const float* __restrict__ bias,
                                                  float* __restrict__ out) {
    const int t = blockIdx.x * 256 + threadIdx.x;   // grid covers NTOK exactly
    int idx = X[t];
    if (idx < 0) idx = 0;
    if (idx >= NUM_LABELS) idx = NUM_LABELS - 1;    // never fault

    const int bin = idx >> 6;
    const int pos = atomicAdd(&g_cursor[bin], 1);
    if (pos < CAP) {
        g_list[bin * CAP + pos] = (t << 6) | (idx & 63);
    } else {
        // Guaranteed-correct slow path; count == 0 in practice.
        float* o = out + (size_t)t * EMBED;
        for (int e = 0; e < EMBED; e++)
            o[e] = W[(size_t)e * NUM_LABELS + idx] + bias[e];
    }
}

// ---------------------------------------------------------------------------
// K2: fused transpose + scatter + bias.
//   Block b: cp.async W[:, b*64 .. b*64+63] into tile[l][e] (pitch 129,
//   bank = (l+e)%32: conflict-free on both the lane->l write pattern and the
//   lane->e scatter pattern). cp.async = LDGSTS: no destination register, no
//   RAW scoreboard chain, so per-warp MLP is structurally maximal — ptxas
//   cannot sink loads (the R7/R8 failure mode).
//   Then for each token in bin b: out[token][:] = tile[lab][:] + bias
//   (scalar LDS + scalar STG.32, 128B coalesced per warp — R6's measured-good
//   scatter).
// ---------------------------------------------------------------------------
__global__ __launch_bounds__(256) void fused_kernel(const float* __restrict__ W,
                                                    const float* __restrict__ bias,
                                                    float* __restrict__ out) {
    __shared__ float tile[BIN_LABELS][EMBED + 1];   // 33 KB, pitch 129
    __shared__ float bs[EMBED];
    __shared__ int   entries[256];
    __shared__ int   s_count;

    const int bin = blockIdx.x;
    const int l0  = bin << 6;
    const int tid = threadIdx.x;

    if (tid < EMBED) bs[tid] = bias[tid];
    if (tid == 0) {
        s_count = g_cursor[bin];
        g_cursor[bin] = 0;                          // reset for next replay
    }

    // ---- Tile load via cp.async: 32 × 4B per thread, fully decoupled ----
    {
        const int l  = tid & (BIN_LABELS - 1);      // 0..63 (lane -> label)
        const int e0 = tid >> 6;                    // 0..3
        const int lab_g  = l0 + l;
        const bool valid = lab_g < NUM_LABELS;
        const int  src_sz = valid ? 4 : 0;          // 0 => zero-fill, no access
        const int  lab_c  = valid ? lab_g : (NUM_LABELS - 1);  // clamped addr

        const float* wp = W + lab_c;
        #pragma unroll
        for (int k = 0; k < 32; k++) {
            const int e = e0 + 4 * k;               // e in {e0, e0+4, ...}
            const uint32_t dst = smem_u32(&tile[l][e]);
            cp_async_4(dst, wp + (size_t)e * NUM_LABELS, src_sz);
        }
        cp_async_commit_wait_all();
    }
    __syncthreads();

    int count = s_count;
    if (count > CAP) count = CAP;

    const int warp = tid >> 5;
    const int lane = tid & 31;

    for (int base = 0; base < count; base += 256) {
        const int n = min(256, count - base);
        if (tid < n) entries[tid] = g_list[bin * CAP + base + tid];
        __syncthreads();

        for (int i = warp; i < n; i += 8) {         // one warp per token
            const int ent = entries[i];
            const int tok = ent >> 6;
            const int lab = ent & 63;
            float* o = out + (size_t)tok * EMBED;
            #pragma unroll
            for (int k = 0; k < 4; k++) {
                const int e = lane + 32 * k;        // bank (lab+lane)%32: conflict-free
                o[e] = tile[lab][e] + bs[e];
            }
        }
        __syncthreads();                            // entries reusable
    }
}

// ---------------------------------------------------------------------------
// Launch (2 kernels). Inputs identified by element count:
//   65536 -> X (int32), 12800000 -> W (f32 [EMBED,NUM_LABELS]), 128 -> b
// ---------------------------------------------------------------------------
extern "C" void kernel_launch(void* const* d_in, const int* in_sizes, int n_in,
                              void* d_out, int out_size) {
    const int*   X = nullptr;
    const float* W = nullptr;
    const float* b = nullptr;

    for (int i = 0; i < n_in; i++) {
        if (in_sizes[i] == NTOK)                    X = (const int*)d_in[i];
        else if (in_sizes[i] == EMBED * NUM_LABELS) W = (const float*)d_in[i];
        else if (in_sizes[i] == EMBED)              b = (const float*)d_in[i];
    }
    if (!X) X = (const int*)d_in[0];
    if (!W) W = (const float*)d_in[1];
    if (!b) b = (const float*)d_in[2];

    float* out = (float*)d_out;

    bin_kernel<<<NTOK / 256, 256>>>(X, W, b, out);
    fused_kernel<<<NBINS, 256>>>(W, b, out);
}

// round 10
// speedup vs baseline: 1.1539x; 1.1539x over previous
#include <cuda_runtime.h>
#include <stdint.h>

#define NUM_LABELS 100000
#define EMBED      128
#define NTOK       (16 * 4096)

#define BIN_LABELS 64
#define NBINS      ((NUM_LABELS + BIN_LABELS - 1) / BIN_LABELS)   // 1563
#define CAP        1024                                            // slots per bin (mean load 42)

// __device__ scratch (no cudaMalloc). Zero-initialized at module load;
// fused_kernel resets cursors after use so every call starts from zeros.
__device__ int g_cursor[NBINS];
__device__ int g_list[NBINS * CAP];    // packed entries: (token << 6) | local_label

// ---------------------------------------------------------------------------
// K1: bin tokens by 64-label range. entry = (token << 6) | (label % 64).
//     Overflow (pos >= CAP, impossible for this input) handled inline.
// ---------------------------------------------------------------------------
__global__ __launch_bounds__(256) void bin_kernel(const int* __restrict__ X,
                                                  const float* __restrict__ W,
                                                  const float* __restrict__ bias,
                                                  float* __restrict__ out) {
    const int t = blockIdx.x * 256 + threadIdx.x;   // grid covers NTOK exactly
    int idx = X[t];
    if (idx < 0) idx = 0;
    if (idx >= NUM_LABELS) idx = NUM_LABELS - 1;    // never fault

    const int bin = idx >> 6;
    const int pos = atomicAdd(&g_cursor[bin], 1);
    if (pos < CAP) {
        g_list[bin * CAP + pos] = (t << 6) | (idx & 63);
    } else {
        // Guaranteed-correct slow path; count == 0 in practice.
        float* o = out + (size_t)t * EMBED;
        for (int e = 0; e < EMBED; e++)
            o[e] = W[(size_t)e * NUM_LABELS + idx] + bias[e];
    }
}

// ---------------------------------------------------------------------------
// K2: fused transpose + scatter + bias — EXACTLY the R6 body that measured
//   ~15.8us (the only fast load pattern across R6-R9), plus cursor self-reset.
//
//   Tile load: scalar LDG interleaved with scalar STS, fully unrolled.
//   ptxas front-batches the 32 scalar loads (1 reg each => hoisting is cheap),
//   giving high MLP_p1. Do NOT vectorize the STS (R7/R8: ptxas sinks loads
//   into 4-load clumps) and do NOT use cp.async (R9: 8cyc LDGSTS floor).
//
//   tile[l][e], pitch 129: bank (l+e)%32 — conflict-free for the fixed-e/
//   lane-varying-l writes AND the fixed-lab/lane-varying-e scatter reads.
//   Scatter: one warp per token, scalar STG.32, 128B coalesced per warp,
//   512B contiguous per token.
// ---------------------------------------------------------------------------
__global__ __launch_bounds__(256) void fused_kernel(const float* __restrict__ W,
                                                    const float* __restrict__ bias,
                                                    float* __restrict__ out) {
    __shared__ float tile[BIN_LABELS][EMBED + 1];   // 33 KB, pitch 129
    __shared__ float bs[EMBED];
    __shared__ int   entries[256];
    __shared__ int   s_count;

    const int bin = blockIdx.x;
    const int l0  = bin << 6;
    const int tid = threadIdx.x;

    if (tid < EMBED) bs[tid] = bias[tid];
    if (tid == 0) {
        s_count = g_cursor[bin];
        g_cursor[bin] = 0;                          // reset for next replay
    }

    // Tile load: lane -> label (coalesced 128B/warp), 32 e-rows per thread.
    {
        const int l  = tid & (BIN_LABELS - 1);      // 0..63
        const int e0 = tid >> 6;                    // 0..3
        const bool valid = (l0 + l) < NUM_LABELS;
        #pragma unroll
        for (int e = e0; e < EMBED; e += 4) {
            tile[l][e] = valid ? W[(size_t)e * NUM_LABELS + (l0 + l)] : 0.0f;
        }
    }
    __syncthreads();

    int count = s_count;
    if (count > CAP) count = CAP;

    const int warp = tid >> 5;
    const int lane = tid & 31;

    for (int base = 0; base < count; base += 256) {
        const int n = min(256, count - base);
        if (tid < n) entries[tid] = g_list[bin * CAP + base + tid];
        __syncthreads();

        for (int i = warp; i < n; i += 8) {         // one warp per token
            const int ent = entries[i];
            const int tok = ent >> 6;
            const int lab = ent & 63;
            float* o = out + (size_t)tok * EMBED;
            #pragma unroll
            for (int k = 0; k < 4; k++) {
                const int e = lane + 32 * k;        // bank (lab+lane)%32: conflict-free
                o[e] = tile[lab][e] + bs[e];
            }
        }
        __syncthreads();                            // entries reusable
    }
}

// ---------------------------------------------------------------------------
// Launch (2 kernels). Inputs identified by element count:
//   65536 -> X (int32), 12800000 -> W (f32 [EMBED,NUM_LABELS]), 128 -> b
// ---------------------------------------------------------------------------
extern "C" void kernel_launch(void* const* d_in, const int* in_sizes, int n_in,
                              void* d_out, int out_size) {
    const int*   X = nullptr;
    const float* W = nullptr;
    const float* b = nullptr;

    for (int i = 0; i < n_in; i++) {
        if (in_sizes[i] == NTOK)                    X = (const int*)d_in[i];
        else if (in_sizes[i] == EMBED * NUM_LABELS) W = (const float*)d_in[i];
        else if (in_sizes[i] == EMBED)              b = (const float*)d_in[i];
    }
    if (!X) X = (const int*)d_in[0];
    if (!W) W = (const float*)d_in[1];
    if (!b) b = (const float*)d_in[2];

    float* out = (float*)d_out;

    bin_kernel<<<NTOK / 256, 256>>>(X, W, b, out);
    fused_kernel<<<NBINS, 256>>>(W, b, out);
}

// round 11
// speedup vs baseline: 1.3900x; 1.2045x over previous
#include <cuda_runtime.h>
#include <stdint.h>

#define NUM_LABELS 100000
#define EMBED      128
#define NTOK       (16 * 4096)

#define BIN_LABELS 32
#define NBINS      (NUM_LABELS / BIN_LABELS)   // 3125, exact — no OOB labels
#define CAP        512                          // slots per bin (mean load ~21)
#define BPC        5                            // bins per CTA
#define GRID       (NBINS / BPC)                // 625 persistent CTAs, single wave

// __device__ scratch (no cudaMalloc). Zero-initialized at module load;
// fused_kernel resets each cursor after reading it, so every call starts
// from zeros (work is identical on every graph replay).
__device__ int g_cursor[NBINS];
__device__ int g_list[NBINS * CAP];    // packed entries: (token << 5) | local_label

__device__ __forceinline__ uint32_t smem_u32(const void* p) {
    uint32_t a;
    asm("{ .reg .u64 t; cvta.to.shared.u64 t, %1; cvt.u32.u64 %0, t; }" : "=r"(a) : "l"(p));
    return a;
}
__device__ __forceinline__ void cp_async_16(uint32_t dst, const void* src) {
    asm volatile("cp.async.cg.shared.global [%0], [%1], 16;\n"
                 :: "r"(dst), "l"(src) : "memory");
}
__device__ __forceinline__ void cp_async_commit() {
    asm volatile("cp.async.commit_group;\n" ::: "memory");
}
__device__ __forceinline__ void cp_async_wait1() {
    asm volatile("cp.async.wait_group 1;\n" ::: "memory");
}
__device__ __forceinline__ void cp_async_wait0() {
    asm volatile("cp.async.wait_group 0;\n" ::: "memory");
}

// ---------------------------------------------------------------------------
// K1: bin tokens by 32-label range. entry = (token << 5) | (label % 32).
//     Overflow (pos >= CAP; needs 25x the mean — impossible here) handled
//     inline by a direct strided gather, so correctness never depends on CAP.
// ---------------------------------------------------------------------------
__global__ __launch_bounds__(256) void bin_kernel(const int* __restrict__ X,
                                                  const float* __restrict__ W,
                                                  const float* __restrict__ bias,
                                                  float* __restrict__ out) {
    const int t = blockIdx.x * 256 + threadIdx.x;   // grid covers NTOK exactly
    int idx = X[t];
    if (idx < 0) idx = 0;
    if (idx >= NUM_LABELS) idx = NUM_LABELS - 1;    // never fault

    const int bin = idx >> 5;
    const int pos = atomicAdd(&g_cursor[bin], 1);
    if (pos < CAP) {
        g_list[bin * CAP + pos] = (t << 5) | (idx & 31);
    } else {
        // Guaranteed-correct slow path; count == 0 in practice.
        float* o = out + (size_t)t * EMBED;
        for (int e = 0; e < EMBED; e++)
            o[e] = W[(size_t)e * NUM_LABELS + idx] + bias[e];
    }
}

// ---------------------------------------------------------------------------
// K2: persistent, double-buffered fused transpose+scatter+bias.
//
//   CTA c owns bins [5c, 5c+5). For each bin: a 32-label x 128-embed tile
//   (16KB) is prefetched into SMEM with cp.async.cg 16B while the PREVIOUS
//   bin's tile is being scattered — the scatter's store traffic and the next
//   tile's load traffic overlap, breaking the R6-R10 load/scatter convoy.
//
//   Tile layout (e-major, 32 words per row, rotation swizzle):
//     phys_word(e, l) = e*32 + ((l + 4*(e&7)) & 31)
//   - cp.async dst chunk p (16B) holds labels 4*((p - (e&7))&7)..+3: both the
//     gmem source and the SMEM destination are 16B-contiguous and aligned.
//   - scatter read (fixed l, e = lane+32k) has a 4-way bank conflict (lanes
//     e, e+8, e+16, e+24 share a bank): 4cyc LDS, negligible vs store path.
//   Global stores: scalar STG.32, 128B coalesced per warp, 512B/token.
// ---------------------------------------------------------------------------
__global__ __launch_bounds__(256) void fused_kernel(const float* __restrict__ W,
                                                    const float* __restrict__ bias,
                                                    float* __restrict__ out) {
    __shared__ float tiles[2][EMBED * BIN_LABELS];  // 2 x 16KB
    __shared__ float bs[EMBED];
    __shared__ int   entries[256];
    __shared__ int   s_count[BPC];

    const int tid = threadIdx.x;
    const int bin0 = blockIdx.x * BPC;

    if (tid < EMBED) bs[tid] = bias[tid];
    if (tid < BPC) {
        s_count[tid] = g_cursor[bin0 + tid];        // read all counts up front
        g_cursor[bin0 + tid] = 0;                   // reset for next replay
    }

    // Per-thread prefetch mapping: e = tid>>1 covers 2 threads per e-row,
    // each thread issues 4 x 16B chunks (p in {4*(tid&1)..+3}).
    const int pe = tid >> 1;                        // 0..127
    const int ps = pe & 7;                          // rotation for this e-row
    const int p0 = (tid & 1) * 4;
    const float* wrow = W + (size_t)pe * NUM_LABELS;
    float* drow_base0 = &tiles[0][pe * BIN_LABELS];
    float* drow_base1 = &tiles[1][pe * BIN_LABELS];

    // Prime the pipeline: prefetch bin0 into buffer 0.
    {
        const int l0 = bin0 * BIN_LABELS;
        #pragma unroll
        for (int k = 0; k < 4; k++) {
            const int p = p0 + k;
            const int soff = 4 * ((p - ps) & 7);
            cp_async_16(smem_u32(drow_base0 + 4 * p), wrow + l0 + soff);
        }
        cp_async_commit();
    }

    const int warp = tid >> 5;
    const int lane = tid & 31;

    #pragma unroll
    for (int j = 0; j < BPC; j++) {
        const int cur = j & 1;
        const int bin = bin0 + j;

        if (j + 1 < BPC) {
            // Prefetch next bin into the other buffer (scattered two iters ago;
            // the trailing __syncthreads of iter j-1 made it safe to overwrite).
            const int l1 = (bin + 1) * BIN_LABELS;
            float* dn = (cur == 0) ? drow_base1 : drow_base0;
            #pragma unroll
            for (int k = 0; k < 4; k++) {
                const int p = p0 + k;
                const int soff = 4 * ((p - ps) & 7);
                cp_async_16(smem_u32(dn + 4 * p), wrow + l1 + soff);
            }
            cp_async_commit();
            cp_async_wait1();                       // current bin's group done
        } else {
            cp_async_wait0();
        }
        __syncthreads();                            // tile[cur] + s_count visible

        int count = s_count[j];
        if (count > CAP) count = CAP;
        const float* tile = tiles[cur];

        for (int base = 0; base < count; base += 256) {
            const int n = min(256, count - base);
            if (tid < n) entries[tid] = g_list[bin * CAP + base + tid];
            __syncthreads();

            for (int i = warp; i < n; i += 8) {     // one warp per token
                const int ent = entries[i];
                const int tok = ent >> 5;
                const int lab = ent & 31;
                float* o = out + (size_t)tok * EMBED;
                #pragma unroll
                for (int k = 0; k < 4; k++) {
                    const int e = lane + 32 * k;
                    const float v = tile[e * BIN_LABELS + ((lab + 4 * (e & 7)) & 31)];
                    o[e] = v + bs[e];
                }
            }
            __syncthreads();                        // entries + tile[cur] reusable
        }
    }
}

// ---------------------------------------------------------------------------
// Launch (2 kernels). Inputs identified by element count:
//   65536 -> X (int32), 12800000 -> W (f32 [EMBED,NUM_LABELS]), 128 -> b
// ---------------------------------------------------------------------------
extern "C" void kernel_launch(void* const* d_in, const int* in_sizes, int n_in,
                              void* d_out, int out_size) {
    const int*   X = nullptr;
    const float* W = nullptr;
    const float* b = nullptr;

    for (int i = 0; i < n_in; i++) {
        if (in_sizes[i] == NTOK)                    X = (const int*)d_in[i];
        else if (in_sizes[i] == EMBED * NUM_LABELS) W = (const float*)d_in[i];
        else if (in_sizes[i] == EMBED)              b = (const float*)d_in[i];
    }
    if (!X) X = (const int*)d_in[0];
    if (!W) W = (const float*)d_in[1];
    if (!b) b = (const float*)d_in[2];

    float* out = (float*)d_out;

    bin_kernel<<<NTOK / 256, 256>>>(X, W, b, out);
    fused_kernel<<<GRID, 256>>>(W, b, out);
}